// round 1
// baseline (speedup 1.0000x reference)
#include <cuda_runtime.h>

#define BATCH 16
#define CH 3
#define H 1024
#define W 1024
#define KS 7
#define PAD 3
#define TILE_W 128
#define TILE_H 16
#define SW (TILE_W + KS - 1)   // 134
#define SPITCH 136             // pad so rows are 16B-aligned-friendly (544B)
#define SH (TILE_H + KS - 1)   // 22

__global__ __launch_bounds__(512, 2)
void Conv_8443905704574_kernel(const float* __restrict__ img,
                               const float* __restrict__ ker,
                               float* __restrict__ out) {
    __shared__ float s[SH][SPITCH];
    __shared__ float kw[KS * KS];

    const int tid = threadIdx.x;          // 0..511
    if (tid < KS * KS) kw[tid] = ker[tid];

    const int bx = blockIdx.x * TILE_W;
    const int by = blockIdx.y * TILE_H;
    const int b  = blockIdx.z;

    // last channel only (reference broadcasts last channel's conv)
    const float* __restrict__ src = img + ((size_t)b * CH + (CH - 1)) * (size_t)H * W;

    // Stage halo tile into smem, zero-padded at image borders.
    // Consecutive tids hit consecutive gmem columns within a row -> coalesced.
    #pragma unroll
    for (int i = tid; i < SH * SW; i += 512) {
        int r = i / SW;
        int c = i - r * SW;
        int gy = by + r - PAD;
        int gx = bx + c - PAD;
        float v = 0.0f;
        if ((unsigned)gy < (unsigned)H && (unsigned)gx < (unsigned)W)
            v = src[(size_t)gy * W + gx];
        s[r][c] = v;
    }
    __syncthreads();

    const int tx = tid & 31;   // 0..31  -> covers 4 contiguous x-pixels
    const int ty = tid >> 5;   // 0..15  -> output row within tile

    float acc0 = 0.f, acc1 = 0.f, acc2 = 0.f, acc3 = 0.f;

    #pragma unroll
    for (int ky = 0; ky < KS; ky++) {
        // 10 consecutive floats starting at a 16B-aligned smem address
        const float* row = &s[ty + ky][tx * 4];
        float4 a = *(const float4*)(row);
        float4 bq = *(const float4*)(row + 4);
        float2 cq = *(const float2*)(row + 8);
        float v[10] = {a.x, a.y, a.z, a.w, bq.x, bq.y, bq.z, bq.w, cq.x, cq.y};

        #pragma unroll
        for (int kx = 0; kx < KS; kx++) {
            float wgt = kw[ky * KS + kx];  // smem broadcast
            acc0 = fmaf(v[kx + 0], wgt, acc0);
            acc1 = fmaf(v[kx + 1], wgt, acc1);
            acc2 = fmaf(v[kx + 2], wgt, acc2);
            acc3 = fmaf(v[kx + 3], wgt, acc3);
        }
    }

    const int ox = bx + tx * 4;
    const int oy = by + ty;
    float4 r4 = make_float4(acc0, acc1, acc2, acc3);
    size_t base = ((size_t)b * CH) * (size_t)H * W + (size_t)oy * W + ox;

    // broadcast the same result to all 3 channels — coalesced STG.128
    #pragma unroll
    for (int c = 0; c < CH; c++) {
        *(float4*)&out[base + (size_t)c * H * W] = r4;
    }
}

extern "C" void kernel_launch(void* const* d_in, const int* in_sizes, int n_in,
                              void* d_out, int out_size) {
    const float* img = (const float*)d_in[0];
    const float* ker = (const float*)d_in[1];
    float* out = (float*)d_out;

    dim3 grid(W / TILE_W, H / TILE_H, BATCH);  // 8 x 64 x 16
    Conv_8443905704574_kernel<<<grid, 512>>>(img, ker, out);
}

// round 2
// speedup vs baseline: 1.0003x; 1.0003x over previous
#include <cuda_runtime.h>

#define BATCH 16
#define CH 3
#define H 1024
#define W 1024
#define KS 7
#define PAD 3
#define TILE_W 128
#define TILE_H 64
#define SW (TILE_W + KS - 1)   // 134
#define SPITCH 136             // 544B row pitch: 16B-aligned vector windows
#define SH (TILE_H + KS - 1)   // 70
#define ROWS_PT 4              // output rows per thread

__global__ __launch_bounds__(512, 2)
void Conv_8443905704574_kernel(const float* __restrict__ img,
                               const float* __restrict__ ker,
                               float* __restrict__ out) {
    __shared__ float s[SH][SPITCH];   // 38080 B
    __shared__ float kw[KS * KS];

    const int tid = threadIdx.x;      // 0..511
    if (tid < KS * KS) kw[tid] = ker[tid];

    const int bx = blockIdx.x * TILE_W;
    const int by = blockIdx.y * TILE_H;
    const int b  = blockIdx.z;

    // reference convolves only the LAST channel and broadcasts it
    const float* __restrict__ src = img + ((size_t)b * CH + (CH - 1)) * (size_t)H * W;

    // Stage halo tile (70 x 134) into smem, zero-padded at borders.
    for (int i = tid; i < SH * SW; i += 512) {
        int r = i / SW;
        int c = i - r * SW;
        int gy = by + r - PAD;
        int gx = bx + c - PAD;
        float v = 0.0f;
        if ((unsigned)gy < (unsigned)H && (unsigned)gx < (unsigned)W)
            v = src[(size_t)gy * W + gx];
        s[r][c] = v;
    }
    __syncthreads();

    const int tx = tid & 31;          // 0..31 -> 4 contiguous x-pixels each
    const int ty = tid >> 5;          // 0..15
    const int row0 = ty * ROWS_PT;    // first output row (within tile)

    float acc[ROWS_PT][4];
    #pragma unroll
    for (int o = 0; o < ROWS_PT; o++)
        #pragma unroll
        for (int j = 0; j < 4; j++) acc[o][j] = 0.0f;

    // Sliding row window: input rows row0 .. row0+9 each loaded ONCE,
    // feeding up to 4 output rows (ky = r - o).
    #pragma unroll
    for (int r = 0; r < ROWS_PT + KS - 1; r++) {       // 10 rows
        const float* row = &s[row0 + r][tx * 4];
        float4 a  = *(const float4*)(row);
        float4 b4 = *(const float4*)(row + 4);
        float2 c2 = *(const float2*)(row + 8);
        float v[10] = {a.x, a.y, a.z, a.w, b4.x, b4.y, b4.z, b4.w, c2.x, c2.y};

        #pragma unroll
        for (int o = 0; o < ROWS_PT; o++) {
            const int ky = r - o;
            if (ky >= 0 && ky < KS) {
                #pragma unroll
                for (int kx = 0; kx < KS; kx++) {
                    float wgt = kw[ky * KS + kx];      // smem broadcast
                    acc[o][0] = fmaf(v[kx + 0], wgt, acc[o][0]);
                    acc[o][1] = fmaf(v[kx + 1], wgt, acc[o][1]);
                    acc[o][2] = fmaf(v[kx + 2], wgt, acc[o][2]);
                    acc[o][3] = fmaf(v[kx + 3], wgt, acc[o][3]);
                }
            }
        }
    }

    const int ox = bx + tx * 4;
    #pragma unroll
    for (int o = 0; o < ROWS_PT; o++) {
        const int oy = by + row0 + o;
        float4 r4 = make_float4(acc[o][0], acc[o][1], acc[o][2], acc[o][3]);
        size_t base = ((size_t)b * CH) * (size_t)H * W + (size_t)oy * W + ox;
        #pragma unroll
        for (int c = 0; c < CH; c++)
            *(float4*)&out[base + (size_t)c * H * W] = r4;   // coalesced STG.128
    }
}

extern "C" void kernel_launch(void* const* d_in, const int* in_sizes, int n_in,
                              void* d_out, int out_size) {
    const float* img = (const float*)d_in[0];
    const float* ker = (const float*)d_in[1];
    float* out = (float*)d_out;

    dim3 grid(W / TILE_W, H / TILE_H, BATCH);   // 8 x 16 x 16 = 2048 CTAs
    Conv_8443905704574_kernel<<<grid, 512>>>(img, ker, out);
}

// round 3
// speedup vs baseline: 1.5984x; 1.5980x over previous
#include <cuda_runtime.h>

#define KS 7
#define PAD 3
#define TILE_W 128
#define TILE_H 64
#define SW 136                     // staged row: gx in [bx-4, bx+132), 16B aligned both ends
#define SH 70
#define ROW_CHUNKS 34              // 34 x 16B per row
#define TCHUNKS (SH * ROW_CHUNKS)  // 2380
#define NTILES 2048                // 8x * 16y * 16b
#define GRID_CTAS 304              // 2 per SM on GB300 (152 SMs)
#define BUF_FLOATS (SH * SW)       // 9520
#define SMEM_BYTES (2 * BUF_FLOATS * 4 + 49 * 8)

typedef unsigned long long u64;

__device__ __forceinline__ u64 pk2(float lo, float hi) {
    u64 r; asm("mov.b64 %0, {%1,%2};" : "=l"(r) : "f"(lo), "f"(hi)); return r;
}
__device__ __forceinline__ void fma2(u64& d, u64 a, u64 b) {
    asm("fma.rn.f32x2 %0, %1, %2, %0;" : "+l"(d) : "l"(a), "l"(b));
}
__device__ __forceinline__ void unpk2(u64 v, float& lo, float& hi) {
    asm("mov.b64 {%0,%1}, %2;" : "=f"(lo), "=f"(hi) : "l"(v));
}
__device__ __forceinline__ void cpa16(unsigned dst, const float* src, unsigned nbytes) {
    asm volatile("cp.async.ca.shared.global [%0], [%1], 16, %2;"
                 :: "r"(dst), "l"(src), "r"(nbytes) : "memory");
}

extern __shared__ float smem[];

// Stage one tile's 70x136 halo (zero-padded) into the smem buffer at sbuf.
__device__ __forceinline__ void stage_tile(const float* __restrict__ img, int t,
                                           unsigned sbuf, int tid) {
    int b   = t >> 7;
    int rem = t & 127;
    int by  = (rem >> 3) * TILE_H;
    int bx  = (rem & 7) * TILE_W;
    const float* src = img + ((size_t)b * 3 + 2) * (size_t)(1024 * 1024); // last channel

    #pragma unroll
    for (int k = 0; k < 5; k++) {
        int i = tid + k * 512;
        if (i < TCHUNKS) {
            int r  = i / ROW_CHUNKS;
            int c  = i - r * ROW_CHUNKS;
            int gy = by + r - PAD;
            int gx = bx - 4 + c * 4;
            // chunks are never partially OOB (borders are 4-float aligned)
            unsigned ok = ((unsigned)gy < 1024u && (unsigned)gx < 1024u) ? 16u : 0u;
            const float* p = src + (size_t)(gy & 1023) * 1024 + (gx & 1023); // safe addr; unread if ok==0
            cpa16(sbuf + (unsigned)(r * SW + c * 4) * 4u, p, ok);
        }
    }
    asm volatile("cp.async.commit_group;" ::: "memory");
}

__global__ __launch_bounds__(512, 2)
void Conv_8443905704574_kernel(const float* __restrict__ img,
                               const float* __restrict__ ker,
                               float* __restrict__ out) {
    const int tid = threadIdx.x;
    float* buf0 = smem;
    float* buf1 = smem + BUF_FLOATS;
    u64*   kw2  = (u64*)(smem + 2 * BUF_FLOATS);

    if (tid < 49) {
        float w = ker[tid];
        kw2[tid] = pk2(w, w);      // duplicated pair for f32x2 math
    }

    unsigned sbase;
    asm("{ .reg .u64 t; cvta.to.shared.u64 t, %1; cvt.u32.u64 %0, t; }"
        : "=r"(sbase) : "l"(smem));
    const unsigned sb0 = sbase;
    const unsigned sb1 = sbase + BUF_FLOATS * 4;

    const int tx   = tid & 31;   // 4 contiguous output x per thread
    const int ty   = tid >> 5;
    const int row0 = ty * 4;     // 4 output rows per thread

    int t = blockIdx.x;
    if (t < NTILES) stage_tile(img, t, sb0, tid);
    int cur = 0;

    while (t < NTILES) {
        int nxt = t + GRID_CTAS;
        if (nxt < NTILES) {
            stage_tile(img, nxt, cur ? sb0 : sb1, tid);
            asm volatile("cp.async.wait_group 1;" ::: "memory");
        } else {
            asm volatile("cp.async.wait_group 0;" ::: "memory");
        }
        __syncthreads();

        const float* B = cur ? buf1 : buf0;

        u64 acc01[4], acc23[4];
        #pragma unroll
        for (int o = 0; o < 4; o++) { acc01[o] = 0ull; acc23[o] = 0ull; }

        // sliding 10-row window; each input row loaded once, feeds up to 4 output rows
        #pragma unroll
        for (int r = 0; r < 10; r++) {
            const float* row = B + (row0 + r) * SW + tx * 4;
            float4 A0 = *(const float4*)(row);
            float4 A1 = *(const float4*)(row + 4);
            float4 A2 = *(const float4*)(row + 8);
            // v[i] = row[i]; p[i] = (v[i+1], v[i+2])
            u64 p[9];
            p[0] = pk2(A0.y, A0.z);
            p[1] = pk2(A0.z, A0.w);
            p[2] = pk2(A0.w, A1.x);
            p[3] = pk2(A1.x, A1.y);
            p[4] = pk2(A1.y, A1.z);
            p[5] = pk2(A1.z, A1.w);
            p[6] = pk2(A1.w, A2.x);
            p[7] = pk2(A2.x, A2.y);
            p[8] = pk2(A2.y, A2.z);

            #pragma unroll
            for (int o = 0; o < 4; o++) {
                const int ky = r - o;
                if (ky >= 0 && ky < KS) {
                    #pragma unroll
                    for (int kx = 0; kx < KS; kx++) {
                        u64 ww = kw2[ky * 7 + kx];   // LDS.64 broadcast
                        fma2(acc01[o], p[kx],     ww);
                        fma2(acc23[o], p[kx + 2], ww);
                    }
                }
            }
        }

        // store: broadcast to all 3 channels, streaming hint (never re-read)
        int b   = t >> 7;
        int rem = t & 127;
        int by  = (rem >> 3) * TILE_H;
        int bx  = (rem & 7) * TILE_W;
        int ox  = bx + tx * 4;
        size_t obase = (size_t)b * 3 * 1024 * 1024;
        #pragma unroll
        for (int o = 0; o < 4; o++) {
            float4 r4;
            unpk2(acc01[o], r4.x, r4.y);
            unpk2(acc23[o], r4.z, r4.w);
            size_t off = obase + (size_t)(by + row0 + o) * 1024 + ox;
            #pragma unroll
            for (int c = 0; c < 3; c++)
                __stcs((float4*)(out + off + (size_t)c * 1024 * 1024), r4);
        }

        __syncthreads();   // protect buffer before it is restaged next iteration
        cur ^= 1;
        t = nxt;
    }
}

extern "C" void kernel_launch(void* const* d_in, const int* in_sizes, int n_in,
                              void* d_out, int out_size) {
    const float* img = (const float*)d_in[0];
    const float* ker = (const float*)d_in[1];
    float* out = (float*)d_out;

    cudaFuncSetAttribute(Conv_8443905704574_kernel,
                         cudaFuncAttributeMaxDynamicSharedMemorySize, SMEM_BYTES);
    Conv_8443905704574_kernel<<<GRID_CTAS, 512, SMEM_BYTES>>>(img, ker, out);
}